// round 3
// baseline (speedup 1.0000x reference)
#include <cuda_runtime.h>
#include <cuda_bf16.h>
#include <cstdint>

// Problem: BispectrumCalculator
//   target: [B=32, T=4, N=512] float32
//   y = fft(target, axis=-1)  (complex64)
//   Bx[k,l] = y[k] * conj(y[l]) * y[(l-k) mod N]
//   source[b, 0, k, l] = mean_t Re(Bx);  source[b, 1, k, l] = mean_t Im(Bx)
//   output = concat(flatten(source [32,2,512,512]), flatten(target [32,4,512]))

#define B_DIM 32
#define T_DIM 4
#define N_DIM 512
#define NROWS (B_DIM * T_DIM)        // 128
#define SRC_ELEMS ((size_t)B_DIM * 2 * N_DIM * N_DIM)  // 16,777,216
#define TGT_ELEMS (B_DIM * T_DIM * N_DIM)              // 65,536

// Scratch for FFT results (allocation-free rule: __device__ global).
__device__ float2 g_y[NROWS * N_DIM];

// ---------------------------------------------------------------------------
// Kernel 1: 512-point radix-2 DIT FFT, one row per block, 256 threads.
// ---------------------------------------------------------------------------
__global__ void fft512_kernel(const float* __restrict__ x) {
    __shared__ float2 s[N_DIM];
    const int row = blockIdx.x;          // 0..127
    const int tid = threadIdx.x;         // 0..255
    const float* xr = x + row * N_DIM;

    // Bit-reversed load (9 bits)
    #pragma unroll
    for (int i = tid; i < N_DIM; i += 256) {
        int r = __brev((unsigned)i) >> 23;
        s[r] = make_float2(xr[i], 0.0f);
    }
    __syncthreads();

    // 9 stages, 256 butterflies per stage, one per thread.
    #pragma unroll
    for (int len = 2; len <= N_DIM; len <<= 1) {
        int half = len >> 1;
        int j    = tid & (half - 1);
        int grp  = tid / half;
        int base = grp * len;
        float ang = -6.283185307179586f * (float)j / (float)len;
        float wr, wi;
        __sincosf(ang, &wi, &wr);   // wi = sin, wr = cos
        float2 a = s[base + j];
        float2 b = s[base + j + half];
        float tr = wr * b.x - wi * b.y;
        float ti = wr * b.y + wi * b.x;
        s[base + j]        = make_float2(a.x + tr, a.y + ti);
        s[base + j + half] = make_float2(a.x - tr, a.y - ti);
        __syncthreads();
    }

    #pragma unroll
    for (int i = tid; i < N_DIM; i += 256)
        g_y[row * N_DIM + i] = s[i];
}

// ---------------------------------------------------------------------------
// Kernel 2: bispectrum. One block per (b, k); 512 threads, thread = l.
//   Shared: the 4 FFT rows of batch b (16 KB).
// ---------------------------------------------------------------------------
__global__ __launch_bounds__(512) void bispec_kernel(float* __restrict__ out) {
    __shared__ float2 sh[T_DIM][N_DIM];
    const int b = blockIdx.x >> 9;       // / 512
    const int k = blockIdx.x & (N_DIM - 1);
    const int l = threadIdx.x;

    #pragma unroll
    for (int t = 0; t < T_DIM; t++)
        sh[t][l] = g_y[(b * T_DIM + t) * N_DIM + l];
    __syncthreads();

    // y[k] per t — broadcast from shared into registers.
    float2 yk[T_DIM];
    #pragma unroll
    for (int t = 0; t < T_DIM; t++) yk[t] = sh[t][k];

    const int m = (l - k) & (N_DIM - 1);
    float are = 0.0f, aim = 0.0f;
    #pragma unroll
    for (int t = 0; t < T_DIM; t++) {
        float2 a = yk[t];
        float2 c = sh[t][l];   // y[l]
        float2 d = sh[t][m];   // y[(l-k) mod N]
        // p = y[k] * conj(y[l])
        float pre = a.x * c.x + a.y * c.y;
        float pim = a.y * c.x - a.x * c.y;
        // p * y[m]
        are += pre * d.x - pim * d.y;
        aim += pre * d.y + pim * d.x;
    }

    const size_t nn   = (size_t)N_DIM * N_DIM;
    const size_t base = (size_t)b * 2 * nn + (size_t)k * N_DIM + l;
    out[base]      = are * (1.0f / T_DIM);
    out[base + nn] = aim * (1.0f / T_DIM);
}

// ---------------------------------------------------------------------------
// Kernel 3: append target to output tail.
// ---------------------------------------------------------------------------
__global__ void copy_target_kernel(const float4* __restrict__ src,
                                   float4* __restrict__ dst, int n4) {
    int i = blockIdx.x * blockDim.x + threadIdx.x;
    if (i < n4) dst[i] = src[i];
}

extern "C" void kernel_launch(void* const* d_in, const int* in_sizes, int n_in,
                              void* d_out, int out_size) {
    const float* target = (const float*)d_in[0];
    float* out = (float*)d_out;

    fft512_kernel<<<NROWS, 256>>>(target);
    bispec_kernel<<<B_DIM * N_DIM, 512>>>(out);

    if ((size_t)out_size >= SRC_ELEMS + TGT_ELEMS) {
        int n4 = TGT_ELEMS / 4;  // 16384 float4s
        copy_target_kernel<<<(n4 + 255) / 256, 256>>>(
            (const float4*)target, (float4*)(out + SRC_ELEMS), n4);
    }
}

// round 5
// speedup vs baseline: 1.7910x; 1.7910x over previous
#include <cuda_runtime.h>
#include <cuda_bf16.h>
#include <cstdint>

// BispectrumCalculator: target [B=32, T=4, N=512] f32
//   y = fft(target);  Bx[k,l] = y[k]*conj(y[l])*y[(l-k)%N]
//   source[b,{re,im},k,l] = mean_t Bx;  out = concat(source, target)

#define B_DIM 32
#define T_DIM 4
#define N_DIM 512
#define NROWS (B_DIM * T_DIM)                           // 128
#define SRC_ELEMS ((size_t)B_DIM * 2 * N_DIM * N_DIM)   // 16,777,216
#define TGT_ELEMS (B_DIM * T_DIM * N_DIM)               // 65,536
#define K_PER 8
#define KG_PER_B (N_DIM / K_PER)                        // 64

// FFT results scratch (allocation-free rule: __device__ global).
__device__ float2 g_y[NROWS * N_DIM];

// ---------------------------------------------------------------------------
// Kernel 1: 512-point radix-2 DIT FFT, one row per block, 256 threads.
// ---------------------------------------------------------------------------
__global__ void fft512_kernel(const float* __restrict__ x) {
    __shared__ float2 s[N_DIM];
    const int row = blockIdx.x;
    const int tid = threadIdx.x;
    const float* xr = x + row * N_DIM;

    #pragma unroll
    for (int i = tid; i < N_DIM; i += 256) {
        int r = __brev((unsigned)i) >> 23;   // 9-bit bit reversal
        s[r] = make_float2(xr[i], 0.0f);
    }
    __syncthreads();

    #pragma unroll
    for (int len = 2; len <= N_DIM; len <<= 1) {
        int half = len >> 1;
        int j    = tid & (half - 1);
        int grp  = tid / half;
        int base = grp * len;
        float ang = -6.283185307179586f * (float)j / (float)len;
        float wr, wi;
        __sincosf(ang, &wi, &wr);   // wi = sin, wr = cos
        float2 a = s[base + j];
        float2 b = s[base + j + half];
        float tr = wr * b.x - wi * b.y;
        float ti = wr * b.y + wi * b.x;
        s[base + j]        = make_float2(a.x + tr, a.y + ti);
        s[base + j + half] = make_float2(a.x - tr, a.y - ti);
        __syncthreads();
    }

    #pragma unroll
    for (int i = tid; i < N_DIM; i += 256)
        g_y[row * N_DIM + i] = s[i];
}

// ---------------------------------------------------------------------------
// Kernel 2: bispectrum, K_PER k-values per block.
//   grid = B * 64 blocks, 512 threads (thread = l).
//   c[t] = y[l] hoisted to registers (k-invariant); per k only the
//   y[k] broadcast + y[(l-k)%N] gather hit shared.
//   kg==63 blocks also copy the target tail (replaces a 3rd kernel).
// ---------------------------------------------------------------------------
__global__ __launch_bounds__(512, 2)
void bispec_kernel(const float* __restrict__ target, float* __restrict__ out,
                   int copy_tail) {
    __shared__ float2 sh[T_DIM][N_DIM];
    const int b  = blockIdx.x >> 6;          // / KG_PER_B
    const int kg = blockIdx.x & (KG_PER_B - 1);
    const int l  = threadIdx.x;

    #pragma unroll
    for (int t = 0; t < T_DIM; t++)
        sh[t][l] = g_y[(b * T_DIM + t) * N_DIM + l];

    // Fold the target-tail copy into one block-column (independent of sh).
    if (copy_tail && kg == KG_PER_B - 1) {
        const float4* src = (const float4*)(target + b * T_DIM * N_DIM);
        float4* dst = (float4*)(out + SRC_ELEMS + (size_t)b * T_DIM * N_DIM);
        dst[l] = src[l];                     // 512 float4 = 2048 floats
    }
    __syncthreads();

    // Hoist conj-side operand: c[t] = y_t[l]
    float2 c[T_DIM];
    #pragma unroll
    for (int t = 0; t < T_DIM; t++) c[t] = sh[t][l];

    const size_t nn = (size_t)N_DIM * N_DIM;
    float* out_re = out + (size_t)b * 2 * nn + (size_t)(kg * K_PER) * N_DIM + l;

    #pragma unroll
    for (int kk = 0; kk < K_PER; kk++) {
        const int k = kg * K_PER + kk;
        const int m = (l - k) & (N_DIM - 1);
        float are = 0.0f, aim = 0.0f;
        #pragma unroll
        for (int t = 0; t < T_DIM; t++) {
            float2 a = sh[t][k];   // broadcast
            float2 d = sh[t][m];   // gather, conflict-free (consecutive l)
            // p = y[k] * conj(y[l])
            float pre = a.x * c[t].x + a.y * c[t].y;
            float pim = a.y * c[t].x - a.x * c[t].y;
            // acc += p * y[m]
            are += pre * d.x - pim * d.y;
            aim += pre * d.y + pim * d.x;
        }
        out_re[(size_t)kk * N_DIM]      = are * (1.0f / T_DIM);
        out_re[(size_t)kk * N_DIM + nn] = aim * (1.0f / T_DIM);
    }
}

extern "C" void kernel_launch(void* const* d_in, const int* in_sizes, int n_in,
                              void* d_out, int out_size) {
    const float* target = (const float*)d_in[0];
    float* out = (float*)d_out;

    int copy_tail = ((size_t)out_size >= SRC_ELEMS + TGT_ELEMS) ? 1 : 0;

    fft512_kernel<<<NROWS, 256>>>(target);
    bispec_kernel<<<B_DIM * KG_PER_B, 512>>>(target, out, copy_tail);
}

// round 6
// speedup vs baseline: 2.0867x; 1.1651x over previous
#include <cuda_runtime.h>
#include <cuda_bf16.h>
#include <cstdint>

// BispectrumCalculator: target [B=32, T=4, N=512] f32
//   y = fft(target);  Bx[k,l] = y[k]*conj(y[l])*y[(l-k)%N]
//   source[b,{re,im},k,l] = mean_t Bx;  out = concat(source, target)
//
// Real input => y[N-m] = conj(y[m]) => Bx[l,k] = conj(Bx[k,l]) (Hermitian).
// Compute only upper-triangle 64x64 tiles; mirror via smem transpose.

#define B_DIM 32
#define T_DIM 4
#define N_DIM 512
#define NROWS (B_DIM * T_DIM)                           // 128
#define SRC_ELEMS ((size_t)B_DIM * 2 * N_DIM * N_DIM)   // 16,777,216
#define TGT_ELEMS (B_DIM * T_DIM * N_DIM)               // 65,536
#define TILE 64
#define NT (N_DIM / TILE)                               // 8
#define NTRI (NT * (NT + 1) / 2)                        // 36

// FFT results, t-paired: g_y2[b][p][n] = float4(y_{2p}[n].re, y_{2p}[n].im,
//                                               y_{2p+1}[n].re, y_{2p+1}[n].im)
__device__ float4 g_y2[B_DIM * 2 * N_DIM];

// ---------------------------------------------------------------------------
// Kernel 1: 512-point radix-2 DIT FFT, one row per block, 256 threads.
//           Also copies the target tail into the output.
// ---------------------------------------------------------------------------
__global__ void fft512_kernel(const float* __restrict__ x,
                              float* __restrict__ out, int copy_tail) {
    __shared__ float2 s[N_DIM];
    const int row = blockIdx.x;          // 0..127
    const int tid = threadIdx.x;         // 0..255
    const float* xr = x + row * N_DIM;

    if (copy_tail && tid < 128) {        // 128 float4 = 512 floats per row
        ((float4*)(out + SRC_ELEMS + (size_t)row * N_DIM))[tid] =
            ((const float4*)xr)[tid];
    }

    #pragma unroll
    for (int i = tid; i < N_DIM; i += 256) {
        int r = __brev((unsigned)i) >> 23;   // 9-bit bit reversal
        s[r] = make_float2(xr[i], 0.0f);
    }
    __syncthreads();

    #pragma unroll
    for (int len = 2; len <= N_DIM; len <<= 1) {
        int half = len >> 1;
        int j    = tid & (half - 1);
        int grp  = tid / half;
        int base = grp * len;
        float ang = -6.283185307179586f * (float)j / (float)len;
        float wr, wi;
        __sincosf(ang, &wi, &wr);
        float2 a = s[base + j];
        float2 b = s[base + j + half];
        float tr = wr * b.x - wi * b.y;
        float ti = wr * b.y + wi * b.x;
        s[base + j]        = make_float2(a.x + tr, a.y + ti);
        s[base + j + half] = make_float2(a.x - tr, a.y - ti);
        __syncthreads();
    }

    // Paired store: row = b*4 + t -> half (t&1) of float4 at [b*2 + t/2][i]
    const int b = row >> 2, t = row & 3;
    float2* dst = (float2*)g_y2 + ((size_t)((b * 2 + (t >> 1)) * N_DIM)) * 2 + (t & 1);
    #pragma unroll
    for (int i = tid; i < N_DIM; i += 256)
        dst[i * 2] = s[i];
}

// ---------------------------------------------------------------------------
// Kernel 2: bispectrum on upper-triangle tiles.
//   grid = (36, 32); block = 512 threads.
//   Dynamic smem: sy[2][512] float4 (16KB) + stre/stim[64][65] (33.3KB).
// ---------------------------------------------------------------------------
__global__ __launch_bounds__(512, 2)
void bispec_kernel(float* __restrict__ out) {
    extern __shared__ float dsm[];
    float4* sy   = (float4*)dsm;          // 1024 float4
    float*  stre = dsm + 4096;            // 64*65 floats
    float*  stim = stre + 64 * 65;

    const int b   = blockIdx.y;
    const int tid = threadIdx.x;
    const int tx  = tid & 63;             // l within tile
    const int tyg = tid >> 6;             // 0..7, k sub-group

    // Triangle index -> (ti, tj), tj >= ti
    int q = blockIdx.x, ti = 0, span = NT;
    while (q >= span) { q -= span; span--; ti++; }
    const int tj = ti + q;
    const int K0 = ti * TILE;
    const int L0 = tj * TILE;

    // Load y tile-pair arrays (1024 float4 / 512 threads = 2 each)
    const float4* gy = g_y2 + (size_t)b * (2 * N_DIM);
    sy[tid]       = gy[tid];
    sy[tid + 512] = gy[tid + 512];
    __syncthreads();

    const int l = L0 + tx;
    const float4 c01 = sy[l];             // conj side, t0/t1
    const float4 c23 = sy[N_DIM + l];     // conj side, t2/t3

    const size_t nn = (size_t)N_DIM * N_DIM;
    float* out_b = out + (size_t)b * 2 * nn;

    #pragma unroll
    for (int kk = 0; kk < 8; kk++) {
        const int kloc = tyg * 8 + kk;
        const int k = K0 + kloc;
        const int m = (l - k) & (N_DIM - 1);

        float are = 0.0f, aim = 0.0f;
        {
            float4 A = sy[k];
            float4 D = sy[m];
            float pre = A.x * c01.x + A.y * c01.y;
            float pim = A.y * c01.x - A.x * c01.y;
            are += pre * D.x - pim * D.y;
            aim += pre * D.y + pim * D.x;
            pre = A.z * c01.z + A.w * c01.w;
            pim = A.w * c01.z - A.z * c01.w;
            are += pre * D.z - pim * D.w;
            aim += pre * D.w + pim * D.z;
        }
        {
            float4 A = sy[N_DIM + k];
            float4 D = sy[N_DIM + m];
            float pre = A.x * c23.x + A.y * c23.y;
            float pim = A.y * c23.x - A.x * c23.y;
            are += pre * D.x - pim * D.y;
            aim += pre * D.y + pim * D.x;
            pre = A.z * c23.z + A.w * c23.w;
            pim = A.w * c23.z - A.z * c23.w;
            are += pre * D.z - pim * D.w;
            aim += pre * D.w + pim * D.z;
        }
        are *= 0.25f;
        aim *= 0.25f;

        const size_t o = (size_t)k * N_DIM + l;
        out_b[o]      = are;
        out_b[o + nn] = aim;
        stre[kloc * 65 + tx] = are;
        stim[kloc * 65 + tx] = aim;
    }

    if (ti == tj) return;                 // diagonal tile: no mirror

    __syncthreads();

    // Mirror tile: out[L0+r][K0+tx] = conj(Bx[K0+tx][L0+r])
    #pragma unroll
    for (int kk = 0; kk < 8; kk++) {
        const int r = tyg * 8 + kk;
        const float re = stre[tx * 65 + r];
        const float im = stim[tx * 65 + r];
        const size_t o = (size_t)(L0 + r) * N_DIM + (K0 + tx);
        out_b[o]      = re;
        out_b[o + nn] = -im;
    }
}

extern "C" void kernel_launch(void* const* d_in, const int* in_sizes, int n_in,
                              void* d_out, int out_size) {
    const float* target = (const float*)d_in[0];
    float* out = (float*)d_out;

    const int copy_tail = ((size_t)out_size >= SRC_ELEMS + TGT_ELEMS) ? 1 : 0;

    const int smem_bytes = (4096 + 2 * 64 * 65) * (int)sizeof(float);  // 49,664
    static bool attr_set = false;
    if (!attr_set) {
        cudaFuncSetAttribute(bispec_kernel,
                             cudaFuncAttributeMaxDynamicSharedMemorySize,
                             smem_bytes);
        attr_set = true;
    }

    fft512_kernel<<<NROWS, 256>>>(target, out, copy_tail);
    bispec_kernel<<<dim3(NTRI, B_DIM), 512, smem_bytes>>>(out);
}